// round 10
// baseline (speedup 1.0000x reference)
#include <cuda_runtime.h>
#include <cstdint>

// FreqActivation (real-part output):
//   F(a,p) = relu(a) * cos(pi * tanh(p))
//   out(b,h,w,c) = F(in(b,h,w,c))           if h==0 || w==0 || h+w<=256  (direct D)
//                = F(in(b,256-h,256-w,c))   otherwise (conj keeps Re)
// Compact grid over direct cells only (33151 per b-slice), 8 threads/cell.
// Cache policy: INPUT is streamed (ld.global.cs, evict-first) so the 67MB
// OUTPUT owns L2 (default write-back stores) and stays resident across graph
// replays -> dirty lines are overwritten in place, DRAM writes collapse.

#define HW 256
#define N1 33151u                 // live cells per b-slice
#define NLIVE (8u * N1)           // 265208 live cells
#define TOTTHREADS (NLIVE * 8u)   // 2,121,664 threads (8 per cell = 32 channels)

__device__ __forceinline__ float fast_cos(float x) {
    float r; asm("cos.approx.f32 %0, %1;" : "=f"(r) : "f"(x)); return r;
}
__device__ __forceinline__ float fast_tanh(float x) {
    const float LOG2E_2 = 2.88539008177792681472f;  // 2*log2(e)
    float e; asm("ex2.approx.f32 %0, %1;" : "=f"(e) : "f"(x * LOG2E_2));
    float r; asm("rcp.approx.f32 %0, %1;" : "=f"(r) : "f"(e + 1.0f));
    return fmaf(-2.0f, r, 1.0f);
}
__device__ __forceinline__ float chan(float amp, float ph) {
    const float PI_F = 3.14159265358979323846f;
    return fmaxf(amp, 0.0f) * fast_cos(PI_F * fast_tanh(ph));
}

// 32-byte STREAMING load (evict-first: keep input out of L2).
__device__ __forceinline__ void ld32_stream(const void* p, float f[8]) {
    uint64_t d0, d1, d2, d3;
    asm volatile("ld.global.cs.v4.b64 {%0,%1,%2,%3}, [%4];"
                 : "=l"(d0), "=l"(d1), "=l"(d2), "=l"(d3) : "l"(p));
    f[0] = __uint_as_float((unsigned)d0); f[1] = __uint_as_float((unsigned)(d0 >> 32));
    f[2] = __uint_as_float((unsigned)d1); f[3] = __uint_as_float((unsigned)(d1 >> 32));
    f[4] = __uint_as_float((unsigned)d2); f[5] = __uint_as_float((unsigned)(d2 >> 32));
    f[6] = __uint_as_float((unsigned)d3); f[7] = __uint_as_float((unsigned)(d3 >> 32));
}

// ---------------- real-only output path (out_size = 16,777,216 float32) -------------
__global__ __launch_bounds__(256)
void freq_act_real_kernel(const float4* __restrict__ in, float4* __restrict__ out,
                          unsigned in_cap4, unsigned out_cap4) {
    unsigned tid = blockIdx.x * blockDim.x + threadIdx.x;
    if (tid >= TOTTHREADS) return;
    unsigned s = tid >> 3;          // live-cell index across all b
    unsigned q = tid & 7u;          // 4-channel chunk within cell (0..7)
    unsigned b = s / N1;            // const-div -> mul.hi
    unsigned r = s - b * N1;        // live-cell index within slice

    unsigned h, w;
    if (r < 512u) {                 // rows 0 and 1, each width 256
        h = r >> 8;  w = r & 255u;
    } else {
        unsigned r2 = r - 512u;     // rows 2..255 as 127 pairs of combined width 257
        unsigned v  = r2 / 257u;    // const-div -> mul.hi  (v = 0..126)
        unsigned k  = r2 - v * 257u;
        unsigned wa = 254u - v;     // row (v+2): w in 0..254-v
        bool first = (k <= wa);
        h = first ? (v + 2u) : (255u - v);
        w = first ? k        : (k - (255u - v));
    }
    unsigned hw = h + w;
    unsigned cell = (b << 16) | (h << 8) | w;

    unsigned ii = cell * 16u + 2u * q;        // float4 index (32B-aligned pair)
    if (ii + 1u >= in_cap4) return;
    float f[8];                                // amp0 ph0 ... amp3 ph3
    ld32_stream(&in[ii], f);

    float4 o;
    o.x = chan(f[0], f[1]);
    o.y = chan(f[2], f[3]);
    o.z = chan(f[4], f[5]);
    o.w = chan(f[6], f[7]);

    unsigned oi = cell * 8u + q;
    if (oi < out_cap4) out[oi] = o;            // default write-back: L2-resident

    if (h >= 1u && w >= 1u && hw <= 255u) {    // unique mirror source
        unsigned mcell = (b << 16) | ((HW - h) << 8) | (HW - w);
        unsigned mo = mcell * 8u + q;
        if (mo < out_cap4) out[mo] = o;        // conj keeps the real part
    }
}

// ---------------- interleaved complex fallback (unused when out is float32) ---------
__device__ __forceinline__ float fast_sin(float x) {
    float r; asm("sin.approx.f32 %0, %1;" : "=f"(r) : "f"(x)); return r;
}
__global__ __launch_bounds__(256)
void freq_act_cplx_kernel(const float4* __restrict__ in, float4* __restrict__ out,
                          unsigned in_cap4, unsigned out_cap4) {
    unsigned tid  = blockIdx.x * blockDim.x + threadIdx.x;
    unsigned cell = tid >> 4;
    unsigned q    = tid & 15u;
    unsigned w    = cell & 255u;
    unsigned h    = (cell >> 8) & 255u;
    unsigned hw   = h + w;
    bool direct = (h == 0u) || (w == 0u) || (hw <= 256u);
    if (!direct) return;
    unsigned ii = cell * 16u + q;
    if (ii >= in_cap4) return;
    float4 v = __ldg(&in[ii]);
    const float PI_F = 3.14159265358979323846f;
    float amp0 = fmaxf(v.x, 0.0f), ph0 = PI_F * fast_tanh(v.y);
    float amp1 = fmaxf(v.z, 0.0f), ph1 = PI_F * fast_tanh(v.w);
    float4 o;
    o.x = amp0 * fast_cos(ph0);  o.y = amp0 * fast_sin(ph0);
    o.z = amp1 * fast_cos(ph1);  o.w = amp1 * fast_sin(ph1);
    unsigned oi = cell * 16u + q;
    if (oi < out_cap4) out[oi] = o;
    if (h >= 1u && w >= 1u && hw <= 255u) {
        unsigned mcell = (cell & ~0xFFFFu) | ((HW - h) << 8) | (HW - w);
        unsigned mo = mcell * 16u + q;
        float4 m; m.x = o.x; m.y = -o.y; m.z = o.z; m.w = -o.w;
        if (mo < out_cap4) out[mo] = m;
    }
}

extern "C" void kernel_launch(void* const* d_in, const int* in_sizes, int n_in,
                              void* d_out, int out_size) {
    (void)n_in;
    const float4* in  = (const float4*)d_in[0];
    float4*       out = (float4*)d_out;
    unsigned in_cap4 = (unsigned)(in_sizes[0] / 4);

    if (out_size <= 16777216) {
        unsigned out_cap4 = (unsigned)(out_size / 4);
        const unsigned grid = (TOTTHREADS + 255u) / 256u;   // 8288 blocks
        freq_act_real_kernel<<<grid, 256>>>(in, out, in_cap4, out_cap4);
    } else {
        long long floats = (out_size >= 134217728) ? (long long)out_size / 4
                                                   : (long long)out_size;
        unsigned out_cap4 = (unsigned)(floats / 4);
        const unsigned total = 524288u * 16u;
        freq_act_cplx_kernel<<<total / 256u, 256>>>(in, out, in_cap4, out_cap4);
    }
}

// round 11
// speedup vs baseline: 1.1254x; 1.1254x over previous
#include <cuda_runtime.h>
#include <cstdint>

// FreqActivation (real-part output):
//   F(a,p) = relu(a) * cos(pi * tanh(p))
//   out(b,h,w,c) = F(in(b,h,w,c))           if h==0 || w==0 || h+w<=256  (direct D)
//                = F(in(b,256-h,256-w,c))   otherwise (conj keeps Re)
// Best measured configuration (R8): compact grid over direct cells only
// (33151 per b-slice), 8 threads/cell, row-pairing tid->(h,w) map,
// 32B evict_last loads, .cs streaming stores, MUFU tanh+cos chain.
// Kernel 17.95us / dur 20.96us / rel_err 2.8e-7 on GB300.

#define HW 256
#define N1 33151u                 // live cells per b-slice
#define NLIVE (8u * N1)           // 265208 live cells
#define TOTTHREADS (NLIVE * 8u)   // 2,121,664 threads (8 per cell = 32 channels)

// tanh via ex2+rcp (abs err ~1e-6), then cos via MUFU (arg in [-pi,pi]).
__device__ __forceinline__ float fast_cos(float x) {
    float r; asm("cos.approx.f32 %0, %1;" : "=f"(r) : "f"(x)); return r;
}
__device__ __forceinline__ float fast_tanh(float x) {
    const float LOG2E_2 = 2.88539008177792681472f;  // 2*log2(e)
    float e; asm("ex2.approx.f32 %0, %1;" : "=f"(e) : "f"(x * LOG2E_2));
    float r; asm("rcp.approx.f32 %0, %1;" : "=f"(r) : "f"(e + 1.0f));
    return fmaf(-2.0f, r, 1.0f);
}
__device__ __forceinline__ float chan(float amp, float ph) {
    const float PI_F = 3.14159265358979323846f;
    return fmaxf(amp, 0.0f) * fast_cos(PI_F * fast_tanh(ph));
}

// 32-byte load with L2 evict_last (.v4.b64 shape required on sm_103).
__device__ __forceinline__ void ld32_keep(const void* p, float f[8]) {
    uint64_t d0, d1, d2, d3;
    asm volatile("ld.global.nc.L2::evict_last.v4.b64 {%0,%1,%2,%3}, [%4];"
                 : "=l"(d0), "=l"(d1), "=l"(d2), "=l"(d3) : "l"(p));
    f[0] = __uint_as_float((unsigned)d0); f[1] = __uint_as_float((unsigned)(d0 >> 32));
    f[2] = __uint_as_float((unsigned)d1); f[3] = __uint_as_float((unsigned)(d1 >> 32));
    f[4] = __uint_as_float((unsigned)d2); f[5] = __uint_as_float((unsigned)(d2 >> 32));
    f[6] = __uint_as_float((unsigned)d3); f[7] = __uint_as_float((unsigned)(d3 >> 32));
}
__device__ __forceinline__ void st_stream(float4* p, float x, float y, float z, float w) {
    asm volatile("st.global.cs.v4.f32 [%0], {%1,%2,%3,%4};"
                 :: "l"(p), "f"(x), "f"(y), "f"(z), "f"(w) : "memory");
}

// ---------------- real-only output path (out_size = 16,777,216 float32) -------------
__global__ __launch_bounds__(256)
void freq_act_real_kernel(const float4* __restrict__ in, float4* __restrict__ out,
                          unsigned in_cap4, unsigned out_cap4) {
    unsigned tid = blockIdx.x * blockDim.x + threadIdx.x;
    if (tid >= TOTTHREADS) return;
    unsigned s = tid >> 3;          // live-cell index across all b
    unsigned q = tid & 7u;          // 4-channel chunk within cell (0..7)
    unsigned b = s / N1;            // const-div -> mul.hi
    unsigned r = s - b * N1;        // live-cell index within slice

    unsigned h, w;
    if (r < 512u) {                 // rows 0 and 1, each width 256
        h = r >> 8;  w = r & 255u;
    } else {
        unsigned r2 = r - 512u;     // rows 2..255 as 127 pairs of combined width 257
        unsigned v  = r2 / 257u;    // const-div -> mul.hi  (v = 0..126)
        unsigned k  = r2 - v * 257u;
        unsigned wa = 254u - v;     // row (v+2): w in 0..254-v
        bool first = (k <= wa);
        h = first ? (v + 2u) : (255u - v);
        w = first ? k        : (k - (255u - v));
    }
    unsigned hw = h + w;
    unsigned cell = (b << 16) | (h << 8) | w;

    unsigned ii = cell * 16u + 2u * q;        // float4 index (32B-aligned pair)
    if (ii + 1u >= in_cap4) return;
    float f[8];                                // amp0 ph0 ... amp3 ph3
    ld32_keep(&in[ii], f);

    float o0 = chan(f[0], f[1]);
    float o1 = chan(f[2], f[3]);
    float o2 = chan(f[4], f[5]);
    float o3 = chan(f[6], f[7]);

    unsigned oi = cell * 8u + q;
    if (oi < out_cap4) st_stream(&out[oi], o0, o1, o2, o3);

    if (h >= 1u && w >= 1u && hw <= 255u) {    // unique mirror source
        unsigned mcell = (b << 16) | ((HW - h) << 8) | (HW - w);
        unsigned mo = mcell * 8u + q;
        if (mo < out_cap4) st_stream(&out[mo], o0, o1, o2, o3);  // conj keeps Re
    }
}

// ---------------- interleaved complex fallback (unused when out is float32) ---------
__device__ __forceinline__ float fast_sin(float x) {
    float r; asm("sin.approx.f32 %0, %1;" : "=f"(r) : "f"(x)); return r;
}
__global__ __launch_bounds__(256)
void freq_act_cplx_kernel(const float4* __restrict__ in, float4* __restrict__ out,
                          unsigned in_cap4, unsigned out_cap4) {
    unsigned tid  = blockIdx.x * blockDim.x + threadIdx.x;
    unsigned cell = tid >> 4;
    unsigned q    = tid & 15u;
    unsigned w    = cell & 255u;
    unsigned h    = (cell >> 8) & 255u;
    unsigned hw   = h + w;
    bool direct = (h == 0u) || (w == 0u) || (hw <= 256u);
    if (!direct) return;
    unsigned ii = cell * 16u + q;
    if (ii >= in_cap4) return;
    float4 v = __ldg(&in[ii]);
    const float PI_F = 3.14159265358979323846f;
    float amp0 = fmaxf(v.x, 0.0f), ph0 = PI_F * fast_tanh(v.y);
    float amp1 = fmaxf(v.z, 0.0f), ph1 = PI_F * fast_tanh(v.w);
    float4 o;
    o.x = amp0 * fast_cos(ph0);  o.y = amp0 * fast_sin(ph0);
    o.z = amp1 * fast_cos(ph1);  o.w = amp1 * fast_sin(ph1);
    unsigned oi = cell * 16u + q;
    if (oi < out_cap4) out[oi] = o;
    if (h >= 1u && w >= 1u && hw <= 255u) {
        unsigned mcell = (cell & ~0xFFFFu) | ((HW - h) << 8) | (HW - w);
        unsigned mo = mcell * 16u + q;
        float4 m; m.x = o.x; m.y = -o.y; m.z = o.z; m.w = -o.w;
        if (mo < out_cap4) out[mo] = m;
    }
}

extern "C" void kernel_launch(void* const* d_in, const int* in_sizes, int n_in,
                              void* d_out, int out_size) {
    (void)n_in;
    const float4* in  = (const float4*)d_in[0];
    float4*       out = (float4*)d_out;
    unsigned in_cap4 = (unsigned)(in_sizes[0] / 4);

    if (out_size <= 16777216) {
        unsigned out_cap4 = (unsigned)(out_size / 4);
        const unsigned grid = (TOTTHREADS + 255u) / 256u;   // 8288 blocks
        freq_act_real_kernel<<<grid, 256>>>(in, out, in_cap4, out_cap4);
    } else {
        long long floats = (out_size >= 134217728) ? (long long)out_size / 4
                                                   : (long long)out_size;
        unsigned out_cap4 = (unsigned)(floats / 4);
        const unsigned total = 524288u * 16u;
        freq_act_cplx_kernel<<<total / 256u, 256>>>(in, out, in_cap4, out_cap4);
    }
}